// round 6
// baseline (speedup 1.0000x reference)
#include <cuda_runtime.h>
#include <cuda_bf16.h>
#include <cstdint>
#include <cstddef>

#define BB 32
#define TT 512
#define DD 512
#define UU 512

// ---------------------------------------------------------------------------
// Device-global scratch (no cudaMalloc allowed)
// ---------------------------------------------------------------------------
__device__ float    g_mx[(size_t)BB * TT * 3 * UU];   // x@kernel + bias
__device__ float    g_rh[BB * UU];                    // fallback exchange buffer
__device__ unsigned g_cnt[8];
__device__ unsigned g_ep[8];

__device__ __forceinline__ float hsig(float x) {
    return fminf(fmaxf(fmaf(0.2f, x, 0.5f), 0.0f), 1.0f);
}

__device__ __forceinline__ uint32_t smem_u32(const void* p) {
    uint32_t a;
    asm("{ .reg .u64 t; cvta.to.shared.u64 t, %1; cvt.u32.u64 %0, t; }"
        : "=r"(a) : "l"(p));
    return a;
}

// ---------------------------------------------------------------------------
// Kernel 1: mx = x @ kernel + bias   (M=16384, N=1536, K=512)
// ---------------------------------------------------------------------------
__global__ __launch_bounds__(256) void mx_gemm(const float* __restrict__ X,
                                               const float* __restrict__ W,
                                               const float* __restrict__ bias) {
    __shared__ float As[16][132];
    __shared__ float Bs[16][68];

    const int tid = threadIdx.x;
    const int m0  = blockIdx.y * 128;
    const int n0  = blockIdx.x * 64;
    const int tm  = tid & 15;
    const int tn  = tid >> 4;

    float acc[8][4];
#pragma unroll
    for (int i = 0; i < 8; i++)
#pragma unroll
        for (int j = 0; j < 4; j++) acc[i][j] = 0.0f;

    for (int kk = 0; kk < DD; kk += 16) {
#pragma unroll
        for (int jj = 0; jj < 2; jj++) {
            int idx = tid + jj * 256;
            int r   = idx >> 2;
            int kq  = (idx & 3) << 2;
            float4 v = *(const float4*)&X[(size_t)(m0 + r) * DD + kk + kq];
            As[kq + 0][r] = v.x;
            As[kq + 1][r] = v.y;
            As[kq + 2][r] = v.z;
            As[kq + 3][r] = v.w;
        }
        {
            int kr = tid >> 4;
            int nq = (tid & 15) << 2;
            float4 v = *(const float4*)&W[(size_t)(kk + kr) * (3 * UU) + n0 + nq];
            *(float4*)&Bs[kr][nq] = v;
        }
        __syncthreads();

#pragma unroll
        for (int k = 0; k < 16; k++) {
            float4 a0 = *(const float4*)&As[k][tm << 2];
            float4 a1 = *(const float4*)&As[k][64 + (tm << 2)];
            float4 b0 = *(const float4*)&Bs[k][tn << 2];
            float af[8] = {a0.x, a0.y, a0.z, a0.w, a1.x, a1.y, a1.z, a1.w};
            float bf[4] = {b0.x, b0.y, b0.z, b0.w};
#pragma unroll
            for (int i = 0; i < 8; i++)
#pragma unroll
                for (int j = 0; j < 4; j++) acc[i][j] = fmaf(af[i], bf[j], acc[i][j]);
        }
        __syncthreads();
    }

    float4 bv = *(const float4*)&bias[n0 + (tn << 2)];
#pragma unroll
    for (int i = 0; i < 8; i++) {
        int m = (i < 4) ? ((tm << 2) + i) : (64 + (tm << 2) + (i - 4));
        float4 o;
        o.x = acc[i][0] + bv.x;
        o.y = acc[i][1] + bv.y;
        o.z = acc[i][2] + bv.z;
        o.w = acc[i][3] + bv.w;
        *(float4*)&g_mx[(size_t)(m0 + m) * (3 * UU) + n0 + (tn << 2)] = o;
    }
}

#define RED2(v) do { \
    (v) += __shfl_xor_sync(0xffffffffu, (v), 8);  \
    (v) += __shfl_xor_sync(0xffffffffu, (v), 16); \
} while (0)

// ===========================================================================
// PRIMARY: DSMEM-exchange GRU. 8 clusters x 16 CTAs (32 cols each, 4 batches),
// 512 threads. Exchange = st.shared::cluster push + mbarrier (count 16).
// ===========================================================================
struct SMD {
    float wh[512 * 32];        // 64 KB
    float hbuf[2][4][512];     // 16 KB  (peer-pushed h, dbl-buffered)
    float rhbuf[2][4][512];    // 16 KB  (peer-pushed r*h)
    float red[4096];           // 16 KB
    float zs[128];
    float hown[128];
    float hval[128];
    float rhv[128];
    unsigned long long mb[4];  // 0,1: hfull[pb]  2,3: rhfull[pb]
};
#define SMD_BYTES ((int)sizeof(SMD))

#define TRYWAIT(bar, par) asm volatile( \
    "{\n .reg .pred P;\n" \
    "W%=:\n mbarrier.try_wait.parity.acquire.cta.shared::cta.b64 P, [%0], %1, 0x989680;\n" \
    " @P bra D%=;\n bra W%=;\nD%=:\n}" :: "r"(bar), "r"(par) : "memory")

#define FENCE_CLU() asm volatile("fence.acq_rel.cluster;" ::: "memory")

__device__ __forceinline__ void push1(uint32_t laddr, unsigned rank, float v) {
    asm volatile(
        "{ .reg .b32 r; mapa.shared::cluster.u32 r, %0, %1; "
        "st.shared::cluster.b32 [r], %2; }"
        :: "r"(laddr), "r"(rank), "r"(__float_as_uint(v)) : "memory");
}
__device__ __forceinline__ void arrive_remote(uint32_t lbar, unsigned rank) {
    asm volatile(
        "{ .reg .b32 r; mapa.shared::cluster.u32 r, %0, %1; "
        "mbarrier.arrive.shared::cluster.b64 _, [r]; }"
        :: "r"(lbar), "r"(rank) : "memory");
}

__global__ __launch_bounds__(512, 1) void gru_dsm(const float* __restrict__ RK,
                                                  float* __restrict__ out) {
    extern __shared__ char raw[];
    SMD* s = (SMD*)raw;
    const int tid = threadIdx.x;
    unsigned rank;
    asm("mov.u32 %0, %%cluster_ctarank;" : "=r"(rank));
    const int grp = blockIdx.x >> 4;
    const int gb0 = grp << 2;
    const int j0  = (int)rank << 5;

    const int ks = tid >> 3;             // 0..63
    const int cs = tid & 7;
    const int ub = ks << 3;
    const int w  = tid >> 5;
    const int l  = tid & 31;

    const int gate = tid >> 7;           // for tid<256
    const int rb   = (tid >> 5) & 3;
    const int rc   = tid & 31;

    // Wh -> SMEM
    for (int i = tid; i < (512 * 32) / 4; i += 512) {
        int f = i << 2;
        int u = f >> 5, c = f & 31;
        *(float4*)&s->wh[f] = *(const float4*)&RK[(size_t)u * 1536 + 1024 + j0 + c];
    }
    // Wz/Wr -> registers
    float wzr[8][4], wrr[8][4];
#pragma unroll
    for (int uu = 0; uu < 8; uu++) {
        const float* bp = &RK[(size_t)(ub + uu) * 1536 + j0 + (cs << 2)];
        float4 a  = *(const float4*)bp;
        float4 b4 = *(const float4*)(bp + 512);
        wzr[uu][0] = a.x;  wzr[uu][1] = a.y;  wzr[uu][2] = a.z;  wzr[uu][3] = a.w;
        wrr[uu][0] = b4.x; wrr[uu][1] = b4.y; wrr[uu][2] = b4.z; wrr[uu][3] = b4.w;
    }
    if (tid < 4) {
        uint32_t ba = smem_u32(&s->mb[tid]);
        asm volatile("mbarrier.init.shared.b64 [%0], %1;" :: "r"(ba), "r"(16u)
                     : "memory");
    }
    __syncthreads();
    // barriers of all CTAs must be live before any remote arrive
    asm volatile("barrier.cluster.arrive.aligned;" ::: "memory");
    asm volatile("barrier.cluster.wait.aligned;" ::: "memory");

    unsigned hph[2] = {0u, 0u}, rph[2] = {0u, 0u};

    // ---- t = 0 : h_prev = 0 ----
    if (tid < 128) {
        size_t mrow = (size_t)(gb0 + rb) * TT * 1536;
        float z  = hsig(g_mx[mrow + j0 + rc]);
        float hh = tanhf(g_mx[mrow + 1024 + j0 + rc]);
        float h0 = (1.0f - z) * hh;
        s->hval[tid] = h0;
        out[(size_t)(gb0 + rb) * TT * UU + j0 + rc] = h0;
    }
    __syncthreads();
    // push h(0) -> hbuf[0] of all 16 CTAs
    {
        int e = tid & 127, b = e >> 5, c = e & 31;
        float v = s->hval[e];
        uint32_t la = smem_u32(&s->hbuf[0][b][j0 + c]);
        int p0 = tid >> 7;
#pragma unroll
        for (int k = 0; k < 4; k++) push1(la, (unsigned)(p0 + (k << 2)), v);
    }
    FENCE_CLU();
    __syncthreads();
    if (tid < 16) arrive_remote(smem_u32(&s->mb[0]), (unsigned)tid);

#pragma unroll 1
    for (int t = 1; t < TT; t++) {
        const int pbh = (t - 1) & 1;   // h buffer to read
        const int pb  = t & 1;         // buffers produced this step

        // prefetch mx gate terms (issue before wait, hide DRAM)
        float pm1 = 0.0f, pm2 = 0.0f;
        if (tid < 256) {
            size_t mrow = ((size_t)(gb0 + rb) * TT + t) * 1536;
            pm1 = __ldcg(&g_mx[mrow + (gate << 9) + j0 + rc]);
            if (tid < 128) pm2 = __ldcg(&g_mx[mrow + 1024 + j0 + rc]);
        }

        // ---- wait h(t-1) ----
        {
            uint32_t ba = smem_u32(&s->mb[pbh]);
            TRYWAIT(ba, hph[pbh]);
            hph[pbh] ^= 1u;
        }
        FENCE_CLU();
        const float* hb = &s->hbuf[pbh][0][0];

        // ---- z pass ----
        {
            float az[4][4];
#pragma unroll
            for (int b = 0; b < 4; b++)
#pragma unroll
                for (int c = 0; c < 4; c++) az[b][c] = 0.0f;
#pragma unroll
            for (int uu = 0; uu < 8; uu++) {
                int u = ub + uu;
                float h0 = hb[u], h1 = hb[512 + u];
                float h2 = hb[1024 + u], h3 = hb[1536 + u];
#pragma unroll
                for (int c = 0; c < 4; c++) {
                    float wv = wzr[uu][c];
                    az[0][c] = fmaf(h0, wv, az[0][c]);
                    az[1][c] = fmaf(h1, wv, az[1][c]);
                    az[2][c] = fmaf(h2, wv, az[2][c]);
                    az[3][c] = fmaf(h3, wv, az[3][c]);
                }
            }
#pragma unroll
            for (int b = 0; b < 4; b++)
#pragma unroll
                for (int c = 0; c < 4; c++) RED2(az[b][c]);
            if (l < 8) {
#pragma unroll
                for (int b = 0; b < 4; b++)
                    *(float4*)&s->red[(w << 8) + (b << 5) + (l << 2)] =
                        make_float4(az[b][0], az[b][1], az[b][2], az[b][3]);
            }
        }
        // ---- r pass ----
        {
            float ar[4][4];
#pragma unroll
            for (int b = 0; b < 4; b++)
#pragma unroll
                for (int c = 0; c < 4; c++) ar[b][c] = 0.0f;
#pragma unroll
            for (int uu = 0; uu < 8; uu++) {
                int u = ub + uu;
                float h0 = hb[u], h1 = hb[512 + u];
                float h2 = hb[1024 + u], h3 = hb[1536 + u];
#pragma unroll
                for (int c = 0; c < 4; c++) {
                    float wv = wrr[uu][c];
                    ar[0][c] = fmaf(h0, wv, ar[0][c]);
                    ar[1][c] = fmaf(h1, wv, ar[1][c]);
                    ar[2][c] = fmaf(h2, wv, ar[2][c]);
                    ar[3][c] = fmaf(h3, wv, ar[3][c]);
                }
            }
#pragma unroll
            for (int b = 0; b < 4; b++)
#pragma unroll
                for (int c = 0; c < 4; c++) RED2(ar[b][c]);
            if (l < 8) {
#pragma unroll
                for (int b = 0; b < 4; b++)
                    *(float4*)&s->red[(w << 8) + 128 + (b << 5) + (l << 2)] =
                        make_float4(ar[b][0], ar[b][1], ar[b][2], ar[b][3]);
            }
        }
        __syncthreads();

        // ---- gates ----
        if (tid < 256) {
            float sum = pm1;
#pragma unroll
            for (int k = 0; k < 16; k++) sum += s->red[(k << 8) + tid];
            float hp = hb[(rb << 9) + j0 + rc];
            if (gate == 0) {
                s->zs[(rb << 5) + rc]   = hsig(sum);
                s->hown[(rb << 5) + rc] = hp;
            } else {
                s->rhv[tid - 128] = hsig(sum) * hp;
            }
        }
        __syncthreads();

        // ---- push rh -> rhbuf[pb] of all CTAs ----
        {
            int e = tid & 127, b = e >> 5, c = e & 31;
            float v = s->rhv[e];
            uint32_t la = smem_u32(&s->rhbuf[pb][b][j0 + c]);
            int p0 = tid >> 7;
#pragma unroll
            for (int k = 0; k < 4; k++) push1(la, (unsigned)(p0 + (k << 2)), v);
        }
        FENCE_CLU();
        __syncthreads();
        if (tid < 16) arrive_remote(smem_u32(&s->mb[2 + pb]), (unsigned)tid);

        // ---- wait rh full ----
        {
            uint32_t ba = smem_u32(&s->mb[2 + pb]);
            TRYWAIT(ba, rph[pb]);
            rph[pb] ^= 1u;
        }
        FENCE_CLU();
        const float* rbp = &s->rhbuf[pb][0][0];

        // ---- h-candidate pass (Wh from SMEM) ----
        {
            float ah[4][4];
#pragma unroll
            for (int b = 0; b < 4; b++)
#pragma unroll
                for (int c = 0; c < 4; c++) ah[b][c] = 0.0f;
#pragma unroll
            for (int uu = 0; uu < 8; uu++) {
                int u = ub + uu;
                float4 wv = *(const float4*)&s->wh[(u << 5) + (cs << 2)];
                float h0 = rbp[u], h1 = rbp[512 + u];
                float h2 = rbp[1024 + u], h3 = rbp[1536 + u];
                ah[0][0] = fmaf(h0, wv.x, ah[0][0]); ah[0][1] = fmaf(h0, wv.y, ah[0][1]);
                ah[0][2] = fmaf(h0, wv.z, ah[0][2]); ah[0][3] = fmaf(h0, wv.w, ah[0][3]);
                ah[1][0] = fmaf(h1, wv.x, ah[1][0]); ah[1][1] = fmaf(h1, wv.y, ah[1][1]);
                ah[1][2] = fmaf(h1, wv.z, ah[1][2]); ah[1][3] = fmaf(h1, wv.w, ah[1][3]);
                ah[2][0] = fmaf(h2, wv.x, ah[2][0]); ah[2][1] = fmaf(h2, wv.y, ah[2][1]);
                ah[2][2] = fmaf(h2, wv.z, ah[2][2]); ah[2][3] = fmaf(h2, wv.w, ah[2][3]);
                ah[3][0] = fmaf(h3, wv.x, ah[3][0]); ah[3][1] = fmaf(h3, wv.y, ah[3][1]);
                ah[3][2] = fmaf(h3, wv.z, ah[3][2]); ah[3][3] = fmaf(h3, wv.w, ah[3][3]);
            }
#pragma unroll
            for (int b = 0; b < 4; b++)
#pragma unroll
                for (int c = 0; c < 4; c++) RED2(ah[b][c]);
            if (l < 8) {
#pragma unroll
                for (int b = 0; b < 4; b++)
                    *(float4*)&s->red[(w << 7) + (b << 5) + (l << 2)] =
                        make_float4(ah[b][0], ah[b][1], ah[b][2], ah[b][3]);
            }
        }
        __syncthreads();

        // ---- final: h(t) ----
        if (tid < 128) {
            float sum = pm2;
#pragma unroll
            for (int k = 0; k < 16; k++) sum += s->red[(k << 7) + tid];
            float hh = tanhf(sum);
            float z  = s->zs[tid];
            float hp = s->hown[tid];
            float hn = z * hp + (1.0f - z) * hh;
            s->hval[tid] = hn;
            out[((size_t)(gb0 + rb) * TT + t) * UU + j0 + rc] = hn;
        }
        __syncthreads();

        if (t < TT - 1) {
            int e = tid & 127, b = e >> 5, c = e & 31;
            float v = s->hval[e];
            uint32_t la = smem_u32(&s->hbuf[pb][b][j0 + c]);
            int p0 = tid >> 7;
#pragma unroll
            for (int k = 0; k < 4; k++) push1(la, (unsigned)(p0 + (k << 2)), v);
            FENCE_CLU();
            __syncthreads();
            if (tid < 16) arrive_remote(smem_u32(&s->mb[pb]), (unsigned)tid);
        }
    }

    // no CTA may exit while peers' DSMEM ops could be in flight
    asm volatile("barrier.cluster.arrive.aligned;" ::: "memory");
    asm volatile("barrier.cluster.wait.aligned;" ::: "memory");
}

// ===========================================================================
// FALLBACK: software-barrier + global exchange (R5 layout, 16-arrive groups)
// ===========================================================================
struct SMW {
    float wh[512 * 32];
    float stage[4][512];
    float red[4096];
    float zs[128];
    float hown[128];
};
#define SMW_BYTES ((int)sizeof(SMW))

__device__ __forceinline__ void bg_sync(int bg, unsigned target) {
    __threadfence();
    __syncthreads();
    if (threadIdx.x == 0) {
        unsigned p = atomicAdd(&g_cnt[bg], 1u);
        if (p == 15u) {
            g_cnt[bg] = 0u;
            __threadfence();
            *(volatile unsigned*)&g_ep[bg] = target;
        } else {
            while (*(volatile unsigned*)&g_ep[bg] < target) { }
        }
    }
    __syncthreads();
}

__global__ __launch_bounds__(512, 1) void gru_sw(const float* __restrict__ RK,
                                                 float* __restrict__ out) {
    extern __shared__ char raw[];
    SMW* s = (SMW*)raw;
    const int tid = threadIdx.x;
    const int grp = blockIdx.x >> 4;
    const int gb0 = grp << 2;
    const int j0  = (blockIdx.x & 15) << 5;

    const int ks = tid >> 3;
    const int cs = tid & 7;
    const int ub = ks << 3;
    const int w  = tid >> 5;
    const int l  = tid & 31;
    const int gate = tid >> 7;
    const int rb   = (tid >> 5) & 3;
    const int rc   = tid & 31;

    for (int i = tid; i < (512 * 32) / 4; i += 512) {
        int f = i << 2;
        int u = f >> 5, c = f & 31;
        *(float4*)&s->wh[f] = *(const float4*)&RK[(size_t)u * 1536 + 1024 + j0 + c];
    }
    float wzr[8][4], wrr[8][4];
#pragma unroll
    for (int uu = 0; uu < 8; uu++) {
        const float* bp = &RK[(size_t)(ub + uu) * 1536 + j0 + (cs << 2)];
        float4 a  = *(const float4*)bp;
        float4 b4 = *(const float4*)(bp + 512);
        wzr[uu][0] = a.x;  wzr[uu][1] = a.y;  wzr[uu][2] = a.z;  wzr[uu][3] = a.w;
        wrr[uu][0] = b4.x; wrr[uu][1] = b4.y; wrr[uu][2] = b4.z; wrr[uu][3] = b4.w;
    }
    __shared__ unsigned ep0;
    if (tid == 0) ep0 = *(volatile unsigned*)&g_ep[grp];
    __syncthreads();
    unsigned tgt = ep0;

    if (tid < 128) {
        size_t mrow = (size_t)(gb0 + rb) * TT * 1536;
        float z  = hsig(g_mx[mrow + j0 + rc]);
        float hh = tanhf(g_mx[mrow + 1024 + j0 + rc]);
        out[(size_t)(gb0 + rb) * TT * UU + j0 + rc] = (1.0f - z) * hh;
    }
    bg_sync(grp, ++tgt);

#pragma unroll 1
    for (int t = 1; t < TT; t++) {
        float pm1 = 0.0f, pm2 = 0.0f;
        if (tid < 256) {
            size_t mrow = ((size_t)(gb0 + rb) * TT + t) * 1536;
            pm1 = __ldcg(&g_mx[mrow + (gate << 9) + j0 + rc]);
            if (tid < 128) pm2 = __ldcg(&g_mx[mrow + 1024 + j0 + rc]);
        }
        {
            int b = tid >> 7, ug = tid & 127;
            float4 v = __ldcg(
                (const float4*)(out + ((size_t)(gb0 + b) * TT + (t - 1)) * UU) + ug);
            *(float4*)&s->stage[b][ug << 2] = v;
        }
        __syncthreads();
        {
            float az[4][4];
#pragma unroll
            for (int b = 0; b < 4; b++)
#pragma unroll
                for (int c = 0; c < 4; c++) az[b][c] = 0.0f;
#pragma unroll
            for (int uu = 0; uu < 8; uu++) {
                int u = ub + uu;
                float h0 = s->stage[0][u], h1 = s->stage[1][u];
                float h2 = s->stage[2][u], h3 = s->stage[3][u];
#pragma unroll
                for (int c = 0; c < 4; c++) {
                    float wv = wzr[uu][c];
                    az[0][c] = fmaf(h0, wv, az[0][c]);
                    az[1][c] = fmaf(h1, wv, az[1][c]);
                    az[2][c] = fmaf(h2, wv, az[2][c]);
                    az[3][c] = fmaf(h3, wv, az[3][c]);
                }
            }
#pragma unroll
            for (int b = 0; b < 4; b++)
#pragma unroll
                for (int c = 0; c < 4; c++) RED2(az[b][c]);
            if (l < 8)
#pragma unroll
                for (int b = 0; b < 4; b++)
                    *(float4*)&s->red[(w << 8) + (b << 5) + (l << 2)] =
                        make_float4(az[b][0], az[b][1], az[b][2], az[b][3]);
        }
        {
            float ar[4][4];
#pragma unroll
            for (int b = 0; b < 4; b++)
#pragma unroll
                for (int c = 0; c < 4; c++) ar[b][c] = 0.0f;
#pragma unroll
            for (int uu = 0; uu < 8; uu++) {
                int u = ub + uu;
                float h0 = s->stage[0][u], h1 = s->stage[1][u];
                float h2 = s->stage[2][u], h3 = s->stage[3][u];
#pragma unroll
                for (int c = 0; c < 4; c++) {
                    float wv = wrr[uu][c];
                    ar[0][c] = fmaf(h0, wv, ar[0][c]);
                    ar[1][c] = fmaf(h1, wv, ar[1][c]);
                    ar[2][c] = fmaf(h2, wv, ar[2][c]);
                    ar[3][c] = fmaf(h3, wv, ar[3][c]);
                }
            }
#pragma unroll
            for (int b = 0; b < 4; b++)
#pragma unroll
                for (int c = 0; c < 4; c++) RED2(ar[b][c]);
            if (l < 8)
#pragma unroll
                for (int b = 0; b < 4; b++)
                    *(float4*)&s->red[(w << 8) + 128 + (b << 5) + (l << 2)] =
                        make_float4(ar[b][0], ar[b][1], ar[b][2], ar[b][3]);
        }
        __syncthreads();
        if (tid < 256) {
            float sum = pm1;
#pragma unroll
            for (int k = 0; k < 16; k++) sum += s->red[(k << 8) + tid];
            float hp = s->stage[rb][j0 + rc];
            if (gate == 0) {
                s->zs[(rb << 5) + rc]   = hsig(sum);
                s->hown[(rb << 5) + rc] = hp;
            } else {
                g_rh[(size_t)(gb0 + rb) * UU + j0 + rc] = hsig(sum) * hp;
            }
        }
        bg_sync(grp, ++tgt);
        {
            int b = tid >> 7, ug = tid & 127;
            float4 v = __ldcg((const float4*)(g_rh + (size_t)(gb0 + b) * UU) + ug);
            *(float4*)&s->stage[b][ug << 2] = v;
        }
        __syncthreads();
        {
            float ah[4][4];
#pragma unroll
            for (int b = 0; b < 4; b++)
#pragma unroll
                for (int c = 0; c < 4; c++) ah[b][c] = 0.0f;
#pragma unroll
            for (int uu = 0; uu < 8; uu++) {
                int u = ub + uu;
                float4 wv = *(const float4*)&s->wh[(u << 5) + (cs << 2)];
                float h0 = s->stage[0][u], h1 = s->stage[1][u];
                float h2 = s->stage[2][u], h3 = s->stage[3][u];
                ah[0][0] = fmaf(h0, wv.x, ah[0][0]); ah[0][1] = fmaf(h0, wv.y, ah[0][1]);
                ah[0][2] = fmaf(h0, wv.z, ah[0][2]); ah[0][3] = fmaf(h0, wv.w, ah[0][3]);
                ah[1][0] = fmaf(h1, wv.x, ah[1][0]); ah[1][1] = fmaf(h1, wv.y, ah[1][1]);
                ah[1][2] = fmaf(h1, wv.z, ah[1][2]); ah[1][3] = fmaf(h1, wv.w, ah[1][3]);
                ah[2][0] = fmaf(h2, wv.x, ah[2][0]); ah[2][1] = fmaf(h2, wv.y, ah[2][1]);
                ah[2][2] = fmaf(h2, wv.z, ah[2][2]); ah[2][3] = fmaf(h2, wv.w, ah[2][3]);
                ah[3][0] = fmaf(h3, wv.x, ah[3][0]); ah[3][1] = fmaf(h3, wv.y, ah[3][1]);
                ah[3][2] = fmaf(h3, wv.z, ah[3][2]); ah[3][3] = fmaf(h3, wv.w, ah[3][3]);
            }
#pragma unroll
            for (int b = 0; b < 4; b++)
#pragma unroll
                for (int c = 0; c < 4; c++) RED2(ah[b][c]);
            if (l < 8)
#pragma unroll
                for (int b = 0; b < 4; b++)
                    *(float4*)&s->red[(w << 7) + (b << 5) + (l << 2)] =
                        make_float4(ah[b][0], ah[b][1], ah[b][2], ah[b][3]);
        }
        __syncthreads();
        if (tid < 128) {
            float sum = pm2;
#pragma unroll
            for (int k = 0; k < 16; k++) sum += s->red[(k << 7) + tid];
            float hh = tanhf(sum);
            float z  = s->zs[tid];
            float hp = s->hown[tid];
            out[((size_t)(gb0 + rb) * TT + t) * UU + j0 + rc] =
                z * hp + (1.0f - z) * hh;
        }
        bg_sync(grp, ++tgt);
    }
}

// ---------------------------------------------------------------------------
extern "C" void kernel_launch(void* const* d_in, const int* in_sizes, int n_in,
                              void* d_out, int out_size) {
    const float* x    = (const float*)d_in[0];
    const float* ker  = (const float*)d_in[1];
    const float* rk   = (const float*)d_in[2];
    const float* bias = (const float*)d_in[3];
    float* out = (float*)d_out;
    (void)in_sizes; (void)n_in; (void)out_size;

    static int mode = -1;
    if (mode < 0) {
        mode = 0;
        cudaError_t e1 = cudaFuncSetAttribute(
            gru_dsm, cudaFuncAttributeMaxDynamicSharedMemorySize, SMD_BYTES);
        cudaError_t e2 = cudaFuncSetAttribute(
            gru_dsm, cudaFuncAttributeNonPortableClusterSizeAllowed, 1);
        if (e1 == cudaSuccess && e2 == cudaSuccess) {
            cudaLaunchConfig_t cfg = {};
            cfg.gridDim  = dim3(128, 1, 1);
            cfg.blockDim = dim3(512, 1, 1);
            cfg.dynamicSmemBytes = SMD_BYTES;
            cudaLaunchAttribute attr[1];
            attr[0].id = cudaLaunchAttributeClusterDimension;
            attr[0].val.clusterDim.x = 16;
            attr[0].val.clusterDim.y = 1;
            attr[0].val.clusterDim.z = 1;
            cfg.attrs = attr;
            cfg.numAttrs = 1;
            int nclu = 0;
            cudaError_t e3 = cudaOccupancyMaxActiveClusters(&nclu, gru_dsm, &cfg);
            if (e3 == cudaSuccess && nclu >= 1) mode = 1;
        }
        cudaGetLastError();
        cudaFuncSetAttribute(gru_sw, cudaFuncAttributeMaxDynamicSharedMemorySize,
                             SMW_BYTES);
    }

    dim3 gg(24, 128);
    mx_gemm<<<gg, 256>>>(x, ker, bias);

    if (mode == 1) {
        cudaLaunchConfig_t cfg = {};
        cfg.gridDim  = dim3(128, 1, 1);
        cfg.blockDim = dim3(512, 1, 1);
        cfg.dynamicSmemBytes = SMD_BYTES;
        cudaLaunchAttribute attr[1];
        attr[0].id = cudaLaunchAttributeClusterDimension;
        attr[0].val.clusterDim.x = 16;
        attr[0].val.clusterDim.y = 1;
        attr[0].val.clusterDim.z = 1;
        cfg.attrs = attr;
        cfg.numAttrs = 1;
        cudaLaunchKernelEx(&cfg, gru_dsm, rk, out);
    } else {
        gru_sw<<<128, 512, SMW_BYTES>>>(rk, out);
    }
}

// round 7
// speedup vs baseline: 1.0211x; 1.0211x over previous
#include <cuda_runtime.h>
#include <cuda_bf16.h>
#include <cstdint>
#include <cstddef>

#define BB 32
#define TT 512
#define DD 512
#define UU 512

// ---------------------------------------------------------------------------
// Device-global scratch (no cudaMalloc allowed)
// ---------------------------------------------------------------------------
__device__ float    g_mx[(size_t)BB * TT * 3 * UU];   // x@kernel + bias
__device__ float    g_rh[BB * UU];                    // r*h exchange buffer
__device__ unsigned g_flags[256];                     // per-CTA step flags

__device__ __forceinline__ float hsig(float x) {
    return fminf(fmaxf(fmaf(0.2f, x, 0.5f), 0.0f), 1.0f);
}

__device__ __forceinline__ void flag_pub(unsigned* p, unsigned v) {
    asm volatile("st.release.gpu.u32 [%0], %1;" :: "l"(p), "r"(v) : "memory");
}
__device__ __forceinline__ unsigned flag_ld(const unsigned* p) {
    unsigned v;
    asm volatile("ld.acquire.gpu.u32 %0, [%1];" : "=r"(v) : "l"(p) : "memory");
    return v;
}

// ---------------------------------------------------------------------------
// Kernel 1: mx = x @ kernel + bias   (M=16384, N=1536, K=512)
// ---------------------------------------------------------------------------
__global__ __launch_bounds__(256) void mx_gemm(const float* __restrict__ X,
                                               const float* __restrict__ W,
                                               const float* __restrict__ bias) {
    __shared__ float As[16][132];
    __shared__ float Bs[16][68];

    const int tid = threadIdx.x;
    const int m0  = blockIdx.y * 128;
    const int n0  = blockIdx.x * 64;
    const int tm  = tid & 15;
    const int tn  = tid >> 4;

    float acc[8][4];
#pragma unroll
    for (int i = 0; i < 8; i++)
#pragma unroll
        for (int j = 0; j < 4; j++) acc[i][j] = 0.0f;

    for (int kk = 0; kk < DD; kk += 16) {
#pragma unroll
        for (int jj = 0; jj < 2; jj++) {
            int idx = tid + jj * 256;
            int r   = idx >> 2;
            int kq  = (idx & 3) << 2;
            float4 v = *(const float4*)&X[(size_t)(m0 + r) * DD + kk + kq];
            As[kq + 0][r] = v.x;
            As[kq + 1][r] = v.y;
            As[kq + 2][r] = v.z;
            As[kq + 3][r] = v.w;
        }
        {
            int kr = tid >> 4;
            int nq = (tid & 15) << 2;
            float4 v = *(const float4*)&W[(size_t)(kk + kr) * (3 * UU) + n0 + nq];
            *(float4*)&Bs[kr][nq] = v;
        }
        __syncthreads();

#pragma unroll
        for (int k = 0; k < 16; k++) {
            float4 a0 = *(const float4*)&As[k][tm << 2];
            float4 a1 = *(const float4*)&As[k][64 + (tm << 2)];
            float4 b0 = *(const float4*)&Bs[k][tn << 2];
            float af[8] = {a0.x, a0.y, a0.z, a0.w, a1.x, a1.y, a1.z, a1.w};
            float bf[4] = {b0.x, b0.y, b0.z, b0.w};
#pragma unroll
            for (int i = 0; i < 8; i++)
#pragma unroll
                for (int j = 0; j < 4; j++) acc[i][j] = fmaf(af[i], bf[j], acc[i][j]);
        }
        __syncthreads();
    }

    float4 bv = *(const float4*)&bias[n0 + (tn << 2)];
#pragma unroll
    for (int i = 0; i < 8; i++) {
        int m = (i < 4) ? ((tm << 2) + i) : (64 + (tm << 2) + (i - 4));
        float4 o;
        o.x = acc[i][0] + bv.x;
        o.y = acc[i][1] + bv.y;
        o.z = acc[i][2] + bv.z;
        o.w = acc[i][3] + bv.w;
        *(float4*)&g_mx[(size_t)(m0 + m) * (3 * UU) + n0 + (tn << 2)] = o;
    }
}

#define RED2(v) do { \
    (v) += __shfl_xor_sync(0xffffffffu, (v), 8);  \
    (v) += __shfl_xor_sync(0xffffffffu, (v), 16); \
} while (0)

// ===========================================================================
// GRU recurrence: 256 CTAs = 8 groups (x4 batches) * 32 col-CTAs (x16 cols),
// 256 threads, 2 CTAs/SM. Sync = per-CTA release/acquire flag words.
// Wz/Wr register-resident; Wh in SMEM.
// ===========================================================================
__global__ __launch_bounds__(256, 2) void gru_f(const float* __restrict__ RK,
                                                float* __restrict__ out) {
    __shared__ float    wh[512 * 16];     // 32 KB
    __shared__ float    stage[4][516];    // h or rh, [b][u]
    __shared__ float    red[1024];
    __shared__ float    zs[64], hown[64];
    __shared__ unsigned sbase;

    const int tid = threadIdx.x;
    const int grp = blockIdx.x >> 5;      // 0..7
    const int cid = blockIdx.x & 31;      // 0..31
    const int gb0 = grp << 2;
    const int j0  = cid << 4;             // 16 unit cols

    const int w    = tid >> 5;
    const int l    = tid & 31;
    const int ks   = (w << 2) | (l >> 3); // 0..31 k-split
    const int tile = l & 7;

    // Wh -> SMEM (512 x 16 floats)
    for (int i = tid; i < 2048; i += 256) {
        int u = i >> 2, c = (i & 3) << 2;
        *(float4*)&wh[(u << 4) + c] =
            *(const float4*)&RK[(size_t)u * 1536 + 1024 + j0 + c];
    }
    // Wz or Wr -> registers: this thread covers 16 u's x 4 cols of z (tile<4)
    // or r (tile>=4)
    float4 wzr[16];
    {
        const float* wbp = RK + (tile < 4 ? 0 : 512) + j0 + ((tile & 3) << 2);
#pragma unroll
        for (int i = 0; i < 16; i++) {
            int u = ks + (i << 5);
            wzr[i] = *(const float4*)&wbp[(size_t)u * 1536];
        }
    }

    if (tid == 0) sbase = flag_ld(&g_flags[blockIdx.x]);
    __syncthreads();
    const unsigned base = sbase;

    // ---- t = 0 : h_prev = 0 ----
    if (tid < 64) {
        int b = tid >> 4, c = tid & 15;
        size_t mrow = (size_t)(gb0 + b) * TT * 1536;
        float z  = hsig(g_mx[mrow + j0 + c]);
        float hh = tanhf(g_mx[mrow + 1024 + j0 + c]);
        out[(size_t)(gb0 + b) * TT * UU + j0 + c] = (1.0f - z) * hh;
    }
    __syncthreads();
    if (tid == 0) flag_pub(&g_flags[blockIdx.x], base + 1u);

#pragma unroll 1
    for (int t = 1; t < TT; t++) {
        // prefetch mx gate terms (independent of sync)
        const int b1 = (tid >> 5) & 3, cc = tid & 31;
        float pm1 = 0.0f, pm2 = 0.0f;
        if (tid < 128) {
            size_t mrow = ((size_t)(gb0 + b1) * TT + t) * 1536;
            pm1 = __ldcg(&g_mx[mrow + (cc < 16 ? (j0 + cc)
                                               : (512 + j0 + (cc - 16)))]);
        }
        if (tid < 64) {
            size_t mrow = ((size_t)(gb0 + (tid >> 4)) * TT + t) * 1536;
            pm2 = __ldcg(&g_mx[mrow + 1024 + j0 + (tid & 15)]);
        }

        // ---- wait: all h(t-1) published (flag >= base + 2t-1) ----
        if (w == 0) {
            const unsigned* fp = &g_flags[(grp << 5) + l];
            unsigned need = (unsigned)(2 * t - 1);
            bool done = (flag_ld(fp) - base) >= need;
            while (!__all_sync(0xffffffffu, done))
                if (!done) done = (flag_ld(fp) - base) >= need;
        }
        __syncthreads();

        // ---- stage h(t-1) ----
#pragma unroll
        for (int it = 0; it < 2; it++) {
            int idx = it * 256 + tid;
            int b = idx >> 7, ug = idx & 127;
            float4 v = __ldcg(
                (const float4*)(out + ((size_t)(gb0 + b) * TT + (t - 1)) * UU) + ug);
            *(float4*)&stage[b][ug << 2] = v;
        }
        __syncthreads();

        // ---- phase 1: z or r pass (register weights) ----
        {
            float a[4][4];
#pragma unroll
            for (int b = 0; b < 4; b++)
#pragma unroll
                for (int c = 0; c < 4; c++) a[b][c] = 0.0f;
#pragma unroll
            for (int i = 0; i < 16; i++) {
                int u = ks + (i << 5);
                float4 wv = wzr[i];
                float h0 = stage[0][u], h1 = stage[1][u];
                float h2 = stage[2][u], h3 = stage[3][u];
                a[0][0] = fmaf(h0, wv.x, a[0][0]); a[0][1] = fmaf(h0, wv.y, a[0][1]);
                a[0][2] = fmaf(h0, wv.z, a[0][2]); a[0][3] = fmaf(h0, wv.w, a[0][3]);
                a[1][0] = fmaf(h1, wv.x, a[1][0]); a[1][1] = fmaf(h1, wv.y, a[1][1]);
                a[1][2] = fmaf(h1, wv.z, a[1][2]); a[1][3] = fmaf(h1, wv.w, a[1][3]);
                a[2][0] = fmaf(h2, wv.x, a[2][0]); a[2][1] = fmaf(h2, wv.y, a[2][1]);
                a[2][2] = fmaf(h2, wv.z, a[2][2]); a[2][3] = fmaf(h2, wv.w, a[2][3]);
                a[3][0] = fmaf(h3, wv.x, a[3][0]); a[3][1] = fmaf(h3, wv.y, a[3][1]);
                a[3][2] = fmaf(h3, wv.z, a[3][2]); a[3][3] = fmaf(h3, wv.w, a[3][3]);
            }
#pragma unroll
            for (int b = 0; b < 4; b++)
#pragma unroll
                for (int c = 0; c < 4; c++) RED2(a[b][c]);
            if (l < 8) {
                int colbase = (l < 4) ? (l << 2) : (16 + ((l - 4) << 2));
#pragma unroll
                for (int b = 0; b < 4; b++)
                    *(float4*)&red[(w << 7) + (b << 5) + colbase] =
                        make_float4(a[b][0], a[b][1], a[b][2], a[b][3]);
            }
        }
        __syncthreads();

        // ---- gates: z -> zs/hown, r -> g_rh ----
        if (tid < 128) {
            float sum = pm1;
#pragma unroll
            for (int k = 0; k < 8; k++) sum += red[(k << 7) + tid];
            if (cc < 16) {
                zs[(b1 << 4) + cc]   = hsig(sum);
                hown[(b1 << 4) + cc] = stage[b1][j0 + cc];
            } else {
                int c = cc - 16;
                g_rh[(size_t)(gb0 + b1) * UU + j0 + c] =
                    hsig(sum) * stage[b1][j0 + c];
            }
        }
        __syncthreads();
        if (tid == 0) flag_pub(&g_flags[blockIdx.x], base + (unsigned)(2 * t));

        // ---- wait: all rh published ----
        if (w == 0) {
            const unsigned* fp = &g_flags[(grp << 5) + l];
            unsigned need = (unsigned)(2 * t);
            bool done = (flag_ld(fp) - base) >= need;
            while (!__all_sync(0xffffffffu, done))
                if (!done) done = (flag_ld(fp) - base) >= need;
        }
        __syncthreads();

        // ---- stage rh ----
#pragma unroll
        for (int it = 0; it < 2; it++) {
            int idx = it * 256 + tid;
            int b = idx >> 7, ug = idx & 127;
            float4 v = __ldcg((const float4*)(g_rh + (size_t)(gb0 + b) * UU) + ug);
            *(float4*)&stage[b][ug << 2] = v;
        }
        __syncthreads();

        // ---- phase 2: h-candidate (Wh from SMEM, 2 cols/thread) ----
        {
            const int c2 = tile << 1;
            float a[4][2];
#pragma unroll
            for (int b = 0; b < 4; b++) { a[b][0] = 0.0f; a[b][1] = 0.0f; }
#pragma unroll
            for (int i = 0; i < 16; i++) {
                int u = ks + (i << 5);
                float2 wv = *(const float2*)&wh[(u << 4) + c2];
                float h0 = stage[0][u], h1 = stage[1][u];
                float h2 = stage[2][u], h3 = stage[3][u];
                a[0][0] = fmaf(h0, wv.x, a[0][0]); a[0][1] = fmaf(h0, wv.y, a[0][1]);
                a[1][0] = fmaf(h1, wv.x, a[1][0]); a[1][1] = fmaf(h1, wv.y, a[1][1]);
                a[2][0] = fmaf(h2, wv.x, a[2][0]); a[2][1] = fmaf(h2, wv.y, a[2][1]);
                a[3][0] = fmaf(h3, wv.x, a[3][0]); a[3][1] = fmaf(h3, wv.y, a[3][1]);
            }
#pragma unroll
            for (int b = 0; b < 4; b++)
#pragma unroll
                for (int c = 0; c < 2; c++) RED2(a[b][c]);
            if (l < 8) {
#pragma unroll
                for (int b = 0; b < 4; b++)
                    *(float2*)&red[(w << 6) + (b << 4) + c2] =
                        make_float2(a[b][0], a[b][1]);
            }
        }
        __syncthreads();

        // ---- final: h(t) = z*h + (1-z)*tanh(...) ----
        if (tid < 64) {
            float sum = pm2;
#pragma unroll
            for (int k = 0; k < 8; k++) sum += red[(k << 6) + tid];
            float hh = tanhf(sum);
            float z  = zs[tid];
            float hp = hown[tid];
            out[((size_t)(gb0 + (tid >> 4)) * TT + t) * UU + j0 + (tid & 15)] =
                z * hp + (1.0f - z) * hh;
        }
        if (t < TT - 1) {
            __syncthreads();
            if (tid == 0)
                flag_pub(&g_flags[blockIdx.x], base + (unsigned)(2 * t + 1));
        }
    }
}

// ---------------------------------------------------------------------------
extern "C" void kernel_launch(void* const* d_in, const int* in_sizes, int n_in,
                              void* d_out, int out_size) {
    const float* x    = (const float*)d_in[0];
    const float* ker  = (const float*)d_in[1];
    const float* rk   = (const float*)d_in[2];
    const float* bias = (const float*)d_in[3];
    float* out = (float*)d_out;
    (void)in_sizes; (void)n_in; (void)out_size;

    dim3 gg(24, 128);
    mx_gemm<<<gg, 256>>>(x, ker, bias);
    gru_f<<<256, 256>>>(rk, out);
}

// round 10
// speedup vs baseline: 1.6746x; 1.6399x over previous
#include <cuda_runtime.h>
#include <cuda_bf16.h>
#include <cstdint>
#include <cstddef>

#define BB 32
#define TT 512
#define DD 512
#define UU 512

// ---------------------------------------------------------------------------
// Device-global scratch (no cudaMalloc allowed)
// ---------------------------------------------------------------------------
__device__ float    g_mx[(size_t)BB * TT * 3 * UU];   // x@kernel + bias
__device__ float    g_rh[BB * UU];                    // r*h exchange buffer
__device__ unsigned g_cnt[8];                         // cumulative arrivals
__device__ unsigned g_ep[8];                          // published epoch = cnt/16

__device__ __forceinline__ float hsig(float x) {
    return fminf(fmaxf(fmaf(0.2f, x, 0.5f), 0.0f), 1.0f);
}

// ---------------------------------------------------------------------------
// Kernel 1: mx = x @ kernel + bias   (M=16384, N=1536, K=512)
// ---------------------------------------------------------------------------
__global__ __launch_bounds__(256) void mx_gemm(const float* __restrict__ X,
                                               const float* __restrict__ W,
                                               const float* __restrict__ bias) {
    __shared__ float As[16][132];
    __shared__ float Bs[16][68];

    const int tid = threadIdx.x;
    const int m0  = blockIdx.y * 128;
    const int n0  = blockIdx.x * 64;
    const int tm  = tid & 15;
    const int tn  = tid >> 4;

    float acc[8][4];
#pragma unroll
    for (int i = 0; i < 8; i++)
#pragma unroll
        for (int j = 0; j < 4; j++) acc[i][j] = 0.0f;

    for (int kk = 0; kk < DD; kk += 16) {
#pragma unroll
        for (int jj = 0; jj < 2; jj++) {
            int idx = tid + jj * 256;
            int r   = idx >> 2;
            int kq  = (idx & 3) << 2;
            float4 v = *(const float4*)&X[(size_t)(m0 + r) * DD + kk + kq];
            As[kq + 0][r] = v.x;
            As[kq + 1][r] = v.y;
            As[kq + 2][r] = v.z;
            As[kq + 3][r] = v.w;
        }
        {
            int kr = tid >> 4;
            int nq = (tid & 15) << 2;
            float4 v = *(const float4*)&W[(size_t)(kk + kr) * (3 * UU) + n0 + nq];
            *(float4*)&Bs[kr][nq] = v;
        }
        __syncthreads();

#pragma unroll
        for (int k = 0; k < 16; k++) {
            float4 a0 = *(const float4*)&As[k][tm << 2];
            float4 a1 = *(const float4*)&As[k][64 + (tm << 2)];
            float4 b0 = *(const float4*)&Bs[k][tn << 2];
            float af[8] = {a0.x, a0.y, a0.z, a0.w, a1.x, a1.y, a1.z, a1.w};
            float bf[4] = {b0.x, b0.y, b0.z, b0.w};
#pragma unroll
            for (int i = 0; i < 8; i++)
#pragma unroll
                for (int j = 0; j < 4; j++) acc[i][j] = fmaf(af[i], bf[j], acc[i][j]);
        }
        __syncthreads();
    }

    float4 bv = *(const float4*)&bias[n0 + (tn << 2)];
#pragma unroll
    for (int i = 0; i < 8; i++) {
        int m = (i < 4) ? ((tm << 2) + i) : (64 + (tm << 2) + (i - 4));
        float4 o;
        o.x = acc[i][0] + bv.x;
        o.y = acc[i][1] + bv.y;
        o.z = acc[i][2] + bv.z;
        o.w = acc[i][3] + bv.w;
        *(float4*)&g_mx[(size_t)(m0 + m) * (3 * UU) + n0 + (tn << 2)] = o;
    }
}

#define RED2(v) do { \
    (v) += __shfl_xor_sync(0xffffffffu, (v), 8);  \
    (v) += __shfl_xor_sync(0xffffffffu, (v), 16); \
} while (0)

// ===========================================================================
// GRU recurrence: 128 CTAs = 8 groups (x4 batches) * 16 col-CTAs (x32 cols),
// 512 threads, 1 CTA/SM. Cumulative-counter arrive + epoch wait (split),
// z-GEMM hidden inside the rh sync window. Wz+Wr in registers, Wh in SMEM.
// ===========================================================================
struct SM16 {
    float wh[512 * 32];     // 64 KB
    float stage[4][512];    // 8 KB (h, then rh)
    float red[16 * 128];    // 8 KB
    float zs[128], hown[128];
    unsigned ep0;
};
#define SM16_BYTES ((int)sizeof(SM16))

__global__ __launch_bounds__(512, 1) void gru16(const float* __restrict__ RK,
                                                float* __restrict__ out) {
    extern __shared__ char raw[];
    SM16* s = (SM16*)raw;
    const int tid = threadIdx.x;
    const int grp = blockIdx.x >> 4;          // 0..7
    const int gb0 = grp << 2;
    const int j0  = (blockIdx.x & 15) << 5;   // 32 unit cols

    const int ks = tid >> 3;                  // 0..63, u = ks*8 .. +7
    const int cs = tid & 7;                   // cols cs*4 .. +3
    const int ub = ks << 3;
    const int w  = tid >> 5;
    const int l  = tid & 31;

    // mapping for gate reductions
    const int gate = tid >> 7;                // tid<256: 0=z, 1=r
    const int rb   = (tid >> 5) & 3;
    const int rc   = tid & 31;

    // ---- weights: Wh -> SMEM, Wz/Wr -> registers ----
    for (int i = tid; i < (512 * 32) / 4; i += 512) {
        int f = i << 2;
        int u = f >> 5, c = f & 31;
        *(float4*)&s->wh[f] = *(const float4*)&RK[(size_t)u * 1536 + 1024 + j0 + c];
    }
    float4 wz[8], wr[8];
#pragma unroll
    for (int uu = 0; uu < 8; uu++) {
        const float* bp = &RK[(size_t)(ub + uu) * 1536 + j0 + (cs << 2)];
        wz[uu] = *(const float4*)bp;
        wr[uu] = *(const float4*)(bp + 512);
    }

    if (tid == 0) s->ep0 = *(volatile unsigned*)&g_ep[grp];
    __syncthreads();
    const unsigned base = s->ep0;
    unsigned tgt = base;

    // Cumulative-counter barrier: no reset, no reset race. Each CTA arrives
    // exactly once per epoch; arrival #16k+15 publishes ep = k+1 (cumulative).
    auto ARRIVE = [&]() {
        __threadfence();
        __syncthreads();
        if (tid == 0) {
            unsigned p = atomicAdd(&g_cnt[grp], 1u);
            if (((p + 1u) & 15u) == 0u) {
                __threadfence();
                *(volatile unsigned*)&g_ep[grp] = (p + 1u) >> 4;
            }
        }
    };
    auto WAIT = [&](unsigned target) {
        if (tid == 0) {
            while ((int)(*(volatile unsigned*)&g_ep[grp] - target) < 0) {
                __nanosleep(32);
            }
        }
        __syncthreads();
    };

    // ---- t = 0 : h_prev = 0 ----
    if (tid < 128) {
        size_t mrow = (size_t)(gb0 + rb) * TT * 1536;
        float z  = hsig(g_mx[mrow + j0 + rc]);
        float hh = tanhf(g_mx[mrow + 1024 + j0 + rc]);
        out[(size_t)(gb0 + rb) * TT * UU + j0 + rc] = (1.0f - z) * hh;
    }
    ARRIVE(); ++tgt;    // h(0) published (tgt = base+1)

#pragma unroll 1
    for (int t = 1; t < TT; t++) {
        // prefetch mx gate terms (independent of sync)
        float pm1 = 0.0f, pm2 = 0.0f;
        if (tid < 256) {
            size_t mrow = ((size_t)(gb0 + rb) * TT + t) * 1536;
            pm1 = __ldcg(&g_mx[mrow + (gate << 9) + j0 + rc]);
            if (tid < 128) pm2 = __ldcg(&g_mx[mrow + 1024 + j0 + rc]);
        }

        // ---- wait h(t-1) published by all group CTAs ----
        WAIT(tgt);

        // ---- stage h(t-1) : 4 x 512 floats ----
        {
            int b = tid >> 7, ug = tid & 127;
            float4 v = __ldcg(
                (const float4*)(out + ((size_t)(gb0 + b) * TT + (t - 1)) * UU) + ug);
            *(float4*)&s->stage[b][ug << 2] = v;
        }
        __syncthreads();

        // ---- r pass (critical path) ----
        {
            float a[4][4];
#pragma unroll
            for (int b = 0; b < 4; b++)
#pragma unroll
                for (int c = 0; c < 4; c++) a[b][c] = 0.0f;
#pragma unroll
            for (int uu = 0; uu < 8; uu++) {
                int u = ub + uu;
                float4 wv = wr[uu];
                float h0 = s->stage[0][u], h1 = s->stage[1][u];
                float h2 = s->stage[2][u], h3 = s->stage[3][u];
                a[0][0] = fmaf(h0, wv.x, a[0][0]); a[0][1] = fmaf(h0, wv.y, a[0][1]);
                a[0][2] = fmaf(h0, wv.z, a[0][2]); a[0][3] = fmaf(h0, wv.w, a[0][3]);
                a[1][0] = fmaf(h1, wv.x, a[1][0]); a[1][1] = fmaf(h1, wv.y, a[1][1]);
                a[1][2] = fmaf(h1, wv.z, a[1][2]); a[1][3] = fmaf(h1, wv.w, a[1][3]);
                a[2][0] = fmaf(h2, wv.x, a[2][0]); a[2][1] = fmaf(h2, wv.y, a[2][1]);
                a[2][2] = fmaf(h2, wv.z, a[2][2]); a[2][3] = fmaf(h2, wv.w, a[2][3]);
                a[3][0] = fmaf(h3, wv.x, a[3][0]); a[3][1] = fmaf(h3, wv.y, a[3][1]);
                a[3][2] = fmaf(h3, wv.z, a[3][2]); a[3][3] = fmaf(h3, wv.w, a[3][3]);
            }
#pragma unroll
            for (int b = 0; b < 4; b++)
#pragma unroll
                for (int c = 0; c < 4; c++) RED2(a[b][c]);
            if (l < 8)
#pragma unroll
                for (int b = 0; b < 4; b++)
                    *(float4*)&s->red[(w << 7) + (b << 5) + (l << 2)] =
                        make_float4(a[b][0], a[b][1], a[b][2], a[b][3]);
        }
        __syncthreads();

        // ---- r reduce -> publish rh (threads 128..255 hold pm1 = mx_r) ----
        if (gate == 1 && tid < 256) {
            int idx = tid - 128;
            float sum = pm1;
#pragma unroll
            for (int k = 0; k < 16; k++) sum += s->red[(k << 7) + idx];
            float r = hsig(sum);
            g_rh[(size_t)(gb0 + rb) * UU + j0 + rc] = r * s->stage[rb][j0 + rc];
        }
        ARRIVE(); ++tgt;          // rh published  (no wait yet)

        // ======== hidden work: z pass while peers publish rh ========
        {
            float a[4][4];
#pragma unroll
            for (int b = 0; b < 4; b++)
#pragma unroll
                for (int c = 0; c < 4; c++) a[b][c] = 0.0f;
#pragma unroll
            for (int uu = 0; uu < 8; uu++) {
                int u = ub + uu;
                float4 wv = wz[uu];
                float h0 = s->stage[0][u], h1 = s->stage[1][u];
                float h2 = s->stage[2][u], h3 = s->stage[3][u];
                a[0][0] = fmaf(h0, wv.x, a[0][0]); a[0][1] = fmaf(h0, wv.y, a[0][1]);
                a[0][2] = fmaf(h0, wv.z, a[0][2]); a[0][3] = fmaf(h0, wv.w, a[0][3]);
                a[1][0] = fmaf(h1, wv.x, a[1][0]); a[1][1] = fmaf(h1, wv.y, a[1][1]);
                a[1][2] = fmaf(h1, wv.z, a[1][2]); a[1][3] = fmaf(h1, wv.w, a[1][3]);
                a[2][0] = fmaf(h2, wv.x, a[2][0]); a[2][1] = fmaf(h2, wv.y, a[2][1]);
                a[2][2] = fmaf(h2, wv.z, a[2][2]); a[2][3] = fmaf(h2, wv.w, a[2][3]);
                a[3][0] = fmaf(h3, wv.x, a[3][0]); a[3][1] = fmaf(h3, wv.y, a[3][1]);
                a[3][2] = fmaf(h3, wv.z, a[3][2]); a[3][3] = fmaf(h3, wv.w, a[3][3]);
            }
#pragma unroll
            for (int b = 0; b < 4; b++)
#pragma unroll
                for (int c = 0; c < 4; c++) RED2(a[b][c]);
            if (l < 8)
#pragma unroll
                for (int b = 0; b < 4; b++)
                    *(float4*)&s->red[(w << 7) + (b << 5) + (l << 2)] =
                        make_float4(a[b][0], a[b][1], a[b][2], a[b][3]);
        }
        __syncthreads();
        if (gate == 0 && tid < 128) {     // threads 0..127 hold pm1 = mx_z
            float sum = pm1;
#pragma unroll
            for (int k = 0; k < 16; k++) sum += s->red[(k << 7) + tid];
            s->zs[tid]   = hsig(sum);
            s->hown[tid] = s->stage[rb][j0 + rc];
        }
        // ============================================================

        // ---- wait rh from all group CTAs, stage it ----
        WAIT(tgt);
        {
            int b = tid >> 7, ug = tid & 127;
            float4 v = __ldcg((const float4*)(g_rh + (size_t)(gb0 + b) * UU) + ug);
            *(float4*)&s->stage[b][ug << 2] = v;
        }
        __syncthreads();

        // ---- h-candidate pass (Wh from SMEM) ----
        {
            float a[4][4];
#pragma unroll
            for (int b = 0; b < 4; b++)
#pragma unroll
                for (int c = 0; c < 4; c++) a[b][c] = 0.0f;
#pragma unroll
            for (int uu = 0; uu < 8; uu++) {
                int u = ub + uu;
                float4 wv = *(const float4*)&s->wh[(u << 5) + (cs << 2)];
                float h0 = s->stage[0][u], h1 = s->stage[1][u];
                float h2 = s->stage[2][u], h3 = s->stage[3][u];
                a[0][0] = fmaf(h0, wv.x, a[0][0]); a[0][1] = fmaf(h0, wv.y, a[0][1]);
                a[0][2] = fmaf(h0, wv.z, a[0][2]); a[0][3] = fmaf(h0, wv.w, a[0][3]);
                a[1][0] = fmaf(h1, wv.x, a[1][0]); a[1][1] = fmaf(h1, wv.y, a[1][1]);
                a[1][2] = fmaf(h1, wv.z, a[1][2]); a[1][3] = fmaf(h1, wv.w, a[1][3]);
                a[2][0] = fmaf(h2, wv.x, a[2][0]); a[2][1] = fmaf(h2, wv.y, a[2][1]);
                a[2][2] = fmaf(h2, wv.z, a[2][2]); a[2][3] = fmaf(h2, wv.w, a[2][3]);
                a[3][0] = fmaf(h3, wv.x, a[3][0]); a[3][1] = fmaf(h3, wv.y, a[3][1]);
                a[3][2] = fmaf(h3, wv.z, a[3][2]); a[3][3] = fmaf(h3, wv.w, a[3][3]);
            }
#pragma unroll
            for (int b = 0; b < 4; b++)
#pragma unroll
                for (int c = 0; c < 4; c++) RED2(a[b][c]);
            if (l < 8)
#pragma unroll
                for (int b = 0; b < 4; b++)
                    *(float4*)&s->red[(w << 7) + (b << 5) + (l << 2)] =
                        make_float4(a[b][0], a[b][1], a[b][2], a[b][3]);
        }
        __syncthreads();

        // ---- final: h(t) ----
        if (tid < 128) {
            float sum = pm2;
#pragma unroll
            for (int k = 0; k < 16; k++) sum += s->red[(k << 7) + tid];
            float hh = tanhf(sum);
            float z  = s->zs[tid];
            float hp = s->hown[tid];
            out[((size_t)(gb0 + rb) * TT + t) * UU + j0 + rc] =
                z * hp + (1.0f - z) * hh;
        }
        ARRIVE(); ++tgt;          // h(t) published; wait at next loop top
    }
}

// ---------------------------------------------------------------------------
extern "C" void kernel_launch(void* const* d_in, const int* in_sizes, int n_in,
                              void* d_out, int out_size) {
    const float* x    = (const float*)d_in[0];
    const float* ker  = (const float*)d_in[1];
    const float* rk   = (const float*)d_in[2];
    const float* bias = (const float*)d_in[3];
    float* out = (float*)d_out;
    (void)in_sizes; (void)n_in; (void)out_size;

    static bool attr_set = false;
    if (!attr_set) {
        cudaFuncSetAttribute(gru16, cudaFuncAttributeMaxDynamicSharedMemorySize,
                             SM16_BYTES);
        attr_set = true;
    }

    dim3 gg(24, 128);
    mx_gemm<<<gg, 256>>>(x, ker, bias);
    gru16<<<128, 512, SM16_BYTES>>>(rk, out);
}